// round 8
// baseline (speedup 1.0000x reference)
#include <cuda_runtime.h>
#include <cuda_bf16.h>
#include <cstdint>

// ---------------------------------------------------------------------------
// RecurrentRetention: B=16, T=2048, D=256, gamma=0.9
//   vsum[b,t] = x[b,t,:].rowsum(Wv);  y[t,e] = sum_b vsum[b,t]*x[b,t,e]
//   c = y @ Wk;  r[t] = 0.9 r[t-1] + c[t] (exact 3-phase scan) -> S
//   out[b,q,p] = S[8p+(q>>8), q&255] * (x @ Wq)[b,q,p]
// GEMMs: warp mma.sync bf16 split (Ah*Bh + Ah*Bl + Al*Bh), operands pre-split
// by producers. This round: 2-stage cp.async double-buffered mainloop.
// ---------------------------------------------------------------------------

#define Bsz 16
#define T   2048
#define D   256
#define LTILE 8
#define NTILE (T / LTILE)             // 256
#define GL 0.43046721f                // 0.9^8

__device__ float g_wvsum[D];
__device__ float g_c[T * D];
__device__ float g_S[T * D];
__device__ float g_carry[NTILE * D];
__device__ float g_pref[NTILE * D];
__device__ __nv_bfloat16 g_xh[Bsz * T * D];
__device__ __nv_bfloat16 g_xl[Bsz * T * D];
__device__ __nv_bfloat16 g_yh[T * D];
__device__ __nv_bfloat16 g_yl[T * D];
__device__ __nv_bfloat16 g_bqh[D * D];  // Wq^T hi, [n][k]
__device__ __nv_bfloat16 g_bql[D * D];
__device__ __nv_bfloat16 g_bkh[D * D];  // Wk^T hi
__device__ __nv_bfloat16 g_bkl[D * D];

__device__ __forceinline__ uint32_t smem_u32(const void* p) {
    uint32_t a;
    asm("{ .reg .u64 t; cvta.to.shared.u64 t, %1; cvt.u32.u64 %0, t; }" : "=r"(a) : "l"(p));
    return a;
}
__device__ __forceinline__ void ldm_x4(uint32_t* r, uint32_t addr) {
    asm volatile("ldmatrix.sync.aligned.m8n8.x4.shared.b16 {%0,%1,%2,%3}, [%4];"
        : "=r"(r[0]), "=r"(r[1]), "=r"(r[2]), "=r"(r[3]) : "r"(addr));
}
__device__ __forceinline__ void ldm_x2(uint32_t* r, uint32_t addr) {
    asm volatile("ldmatrix.sync.aligned.m8n8.x2.shared.b16 {%0,%1}, [%2];"
        : "=r"(r[0]), "=r"(r[1]) : "r"(addr));
}
__device__ __forceinline__ void mma_bf16(float* c, const uint32_t* a, const uint32_t* b) {
    asm volatile(
        "mma.sync.aligned.m16n8k16.row.col.f32.bf16.bf16.f32 "
        "{%0,%1,%2,%3}, {%4,%5,%6,%7}, {%8,%9}, {%0,%1,%2,%3};"
        : "+f"(c[0]), "+f"(c[1]), "+f"(c[2]), "+f"(c[3])
        : "r"(a[0]), "r"(a[1]), "r"(a[2]), "r"(a[3]), "r"(b[0]), "r"(b[1]));
}
__device__ __forceinline__ void cp16(uint32_t sdst, const void* gsrc) {
    asm volatile("cp.async.cg.shared.global [%0], [%1], 16;"
        :: "r"(sdst), "l"(__cvta_generic_to_global(gsrc)));
}
#define CP_COMMIT() asm volatile("cp.async.commit_group;" ::: "memory")
#define CP_WAIT(n)  asm volatile("cp.async.wait_group %0;" :: "n"(n) : "memory")

// ======================= prep: wvsum + Wq/Wk transpose-split ===============
__global__ void prep_kernel(const float* __restrict__ Wq, const float* __restrict__ Wk,
                            const float* __restrict__ Wv) {
    int bx = blockIdx.x, tid = threadIdx.x;
    if (bx < 256) {
        int k = bx, n = tid;
        float w = Wq[k * D + n];
        __nv_bfloat16 h = __float2bfloat16(w);
        g_bqh[n * D + k] = h;
        g_bql[n * D + k] = __float2bfloat16(w - __bfloat162float(h));
    } else if (bx < 512) {
        int k = bx - 256, n = tid;
        float w = Wk[k * D + n];
        __nv_bfloat16 h = __float2bfloat16(w);
        g_bkh[n * D + k] = h;
        g_bkl[n * D + k] = __float2bfloat16(w - __bfloat162float(h));
    } else {
        int row  = (bx - 512) * 8 + (tid >> 5);
        int lane = tid & 31;
        float p = 0.f;
        #pragma unroll
        for (int j = lane; j < D; j += 32) p += Wv[row * D + j];
        #pragma unroll
        for (int off = 16; off; off >>= 1) p += __shfl_xor_sync(0xffffffffu, p, off);
        if (lane == 0) g_wvsum[row] = p;
    }
}

// ======================= y kernel: y split + x split =======================
__global__ void y_kernel(const float* __restrict__ x) {
    __shared__ float xs[Bsz][D];
    __shared__ float vs[Bsz];
    __shared__ float wv[D];
    int t = blockIdx.x;
    int e = threadIdx.x;

    wv[e] = g_wvsum[e];
    #pragma unroll
    for (int b = 0; b < Bsz; ++b) {
        size_t idx = ((size_t)b * T + t) * D + e;
        float v = x[idx];
        xs[b][e] = v;
        __nv_bfloat16 h = __float2bfloat16(v);
        g_xh[idx] = h;
        g_xl[idx] = __float2bfloat16(v - __bfloat162float(h));
    }
    __syncthreads();

    int warp = e >> 5, lane = e & 31;
    #pragma unroll
    for (int rep = 0; rep < 2; ++rep) {
        int b = warp * 2 + rep;
        float p = 0.f;
        #pragma unroll
        for (int k = lane; k < D; k += 32) p += xs[b][k] * wv[k];
        #pragma unroll
        for (int off = 16; off; off >>= 1) p += __shfl_xor_sync(0xffffffffu, p, off);
        if (lane == 0) vs[b] = p;
    }
    __syncthreads();

    float acc = 0.f;
    #pragma unroll
    for (int b = 0; b < Bsz; ++b) acc += vs[b] * xs[b][e];
    __nv_bfloat16 h = __float2bfloat16(acc);
    g_yh[t * D + e] = h;
    g_yl[t * D + e] = __float2bfloat16(acc - __bfloat162float(h));
}

// ======================= unified mma GEMM, 2-stage cp.async ================
// C[m,n] = sum_k A[m,k]*Bt[n,k]; A, Bt pre-split bf16 hi/lo ([row][k], k-major).
// CTA tile (MF*32) x 128, 8 warps = 2(m) x 4(n), warp tile (MF*16) x 32.
#define ROWB 80
template<int MF, bool SCALE>
__global__ void __launch_bounds__(256, 2)
gemm_mma(const __nv_bfloat16* __restrict__ ah, const __nv_bfloat16* __restrict__ al,
         const __nv_bfloat16* __restrict__ bth, const __nv_bfloat16* __restrict__ btl,
         float* __restrict__ C) {
    extern __shared__ char sm[];
    constexpr int ABYTES = MF * 32 * ROWB;
    constexpr int BBYTES = 128 * ROWB;
    constexpr int STAGE  = 2 * ABYTES + 2 * BBYTES;

    int tid = threadIdx.x, wid = tid >> 5, lane = tid & 31;
    int m0 = blockIdx.x * (MF * 32), n0 = blockIdx.y * 128;
    int mwarp = (wid & 1) * (MF * 16), nwarp = (wid >> 1) * 32;

    uint32_t uS = smem_u32(sm);

    float acc[MF][4][4] = {};

    int arow = lane & 15, ao16 = (lane >> 4) * 16;
    int brow = lane & 7,  bo16 = ((lane >> 3) & 1) * 16;

    // ---- async load of one k-chunk into stage st ----
    auto load_chunk = [&](int kc, int st) {
        uint32_t base = uS + st * STAGE;
        #pragma unroll
        for (int i = tid; i < MF * 128; i += 256) {   // A: MF*32 rows x 32 k
            int r = i >> 2, c16 = i & 3;
            size_t goff = (size_t)(m0 + r) * 256 + kc * 32 + c16 * 8;
            uint32_t so = r * ROWB + c16 * 16;
            cp16(base + so,          ah + goff);
            cp16(base + ABYTES + so, al + goff);
        }
        #pragma unroll
        for (int j = 0; j < 2; ++j) {                 // B: 128 rows x 32 k
            int i = tid + j * 256;
            int r = i >> 2, c16 = i & 3;
            size_t goff = (size_t)(n0 + r) * 256 + kc * 32 + c16 * 8;
            uint32_t so = r * ROWB + c16 * 16;
            cp16(base + 2 * ABYTES + so,          bth + goff);
            cp16(base + 2 * ABYTES + BBYTES + so, btl + goff);
        }
        CP_COMMIT();
    };

    load_chunk(0, 0);

    for (int kc = 0; kc < 8; ++kc) {
        if (kc < 7) load_chunk(kc + 1, (kc + 1) & 1);
        if (kc < 7) { CP_WAIT(1); } else { CP_WAIT(0); }
        __syncthreads();

        uint32_t base = uS + (kc & 1) * STAGE;
        uint32_t uAh = base, uAl = base + ABYTES;
        uint32_t uBh = base + 2 * ABYTES, uBl = uBh + BBYTES;

        #pragma unroll
        for (int pass = 0; pass < 3; ++pass) {
            uint32_t uA = (pass < 2) ? uAh : uAl;
            uint32_t uB = (pass == 1) ? uBl : uBh;
            #pragma unroll
            for (int kk = 0; kk < 2; ++kk) {
                uint32_t af[MF][4], bf[4][2];
                #pragma unroll
                for (int mf = 0; mf < MF; ++mf)
                    ldm_x4(af[mf], uA + (mwarp + mf * 16 + arow) * ROWB + kk * 32 + ao16);
                #pragma unroll
                for (int nf = 0; nf < 4; ++nf)
                    ldm_x2(bf[nf], uB + (nwarp + nf * 8 + brow) * ROWB + kk * 32 + bo16);
                #pragma unroll
                for (int mf = 0; mf < MF; ++mf)
                    #pragma unroll
                    for (int nf = 0; nf < 4; ++nf)
                        mma_bf16(acc[mf][nf], af[mf], bf[nf]);
            }
        }
        __syncthreads();   // stage fully consumed before next prefetch reuses it
    }

    // ---- epilogue ----
    int tq = lane >> 2, tr = (lane & 3) * 2;
    #pragma unroll
    for (int mf = 0; mf < MF; ++mf) {
        #pragma unroll
        for (int half = 0; half < 2; ++half) {
            int m = m0 + mwarp + mf * 16 + tq + half * 8;
            size_t obase = (size_t)m * 256;
            int q = m & (T - 1);
            int qh = q >> 8, qc = q & 255;
            #pragma unroll
            for (int nf = 0; nf < 4; ++nf) {
                int n = n0 + nwarp + nf * 8 + tr;
                float2 v;
                if (SCALE) {
                    float s0 = g_S[(((n + 0) << 3) + qh) * 256 + qc];
                    float s1 = g_S[(((n + 1) << 3) + qh) * 256 + qc];
                    v.x = acc[mf][nf][half * 2 + 0] * s0;
                    v.y = acc[mf][nf][half * 2 + 1] * s1;
                } else {
                    v.x = acc[mf][nf][half * 2 + 0];
                    v.y = acc[mf][nf][half * 2 + 1];
                }
                *(float2*)(C + obase + n) = v;
            }
        }
    }
}

// ======================= exact 3-phase scan ================================
__global__ void scanA_kernel() {
    int d = threadIdx.x, g = blockIdx.x;
    int t0 = g * LTILE;
    float s = 0.f;
    #pragma unroll
    for (int i = 0; i < LTILE; ++i) {
        int t = t0 + i;
        float cv = (t == 0) ? 0.f : g_c[t * D + d];
        s = 0.9f * s + cv;
        g_S[t * D + d] = s;
    }
    g_carry[g * D + d] = s;
}
__global__ void scanB_kernel() {
    int d = threadIdx.x;
    float carry = 0.f;
    #pragma unroll 8
    for (int g = 0; g < NTILE; ++g) {
        float tmp = g_carry[g * D + d];
        g_pref[g * D + d] = carry;
        carry = GL * carry + tmp;
    }
}
__global__ void scanC_kernel() {
    int d = threadIdx.x, g = blockIdx.x;
    int t0 = g * LTILE;
    if (g > 0) {
        float pref = g_pref[g * D + d];
        float p = 0.9f;
        #pragma unroll
        for (int i = 0; i < LTILE; ++i) {
            g_S[(t0 + i) * D + d] += p * pref;
            p *= 0.9f;
        }
    } else {
        g_S[d] = g_S[D + d];    // S[0] = r[1]
    }
}

// ======================= launch ============================================
extern "C" void kernel_launch(void* const* d_in, const int* in_sizes, int n_in,
                              void* d_out, int out_size) {
    const float* x  = (const float*)d_in[0];
    const float* Wq = (const float*)d_in[1];
    const float* Wk = (const float*)d_in[2];
    const float* Wv = (const float*)d_in[3];
    float* out = (float*)d_out;

    float* c_p; cudaGetSymbolAddress((void**)&c_p, g_c);
    __nv_bfloat16* xh_p; cudaGetSymbolAddress((void**)&xh_p, g_xh);
    __nv_bfloat16* xl_p; cudaGetSymbolAddress((void**)&xl_p, g_xl);
    __nv_bfloat16* yh_p; cudaGetSymbolAddress((void**)&yh_p, g_yh);
    __nv_bfloat16* yl_p; cudaGetSymbolAddress((void**)&yl_p, g_yl);
    __nv_bfloat16* bqh_p; cudaGetSymbolAddress((void**)&bqh_p, g_bqh);
    __nv_bfloat16* bql_p; cudaGetSymbolAddress((void**)&bql_p, g_bql);
    __nv_bfloat16* bkh_p; cudaGetSymbolAddress((void**)&bkh_p, g_bkh);
    __nv_bfloat16* bkl_p; cudaGetSymbolAddress((void**)&bkl_p, g_bkl);

    // dynamic smem sizes: 2 stages x (2*A + 2*B)
    const int smemC = 2 * (2 * 1 * 32 * ROWB + 2 * 128 * ROWB);   // 51200
    const int smemQ = 2 * (2 * 4 * 32 * ROWB + 2 * 128 * ROWB);   // 81920
    cudaFuncSetAttribute(gemm_mma<1, false>, cudaFuncAttributeMaxDynamicSharedMemorySize, smemC);
    cudaFuncSetAttribute(gemm_mma<4, true>,  cudaFuncAttributeMaxDynamicSharedMemorySize, smemQ);

    prep_kernel<<<544, 256>>>(Wq, Wk, Wv);
    y_kernel<<<T, 256>>>(x);
    {
        dim3 grid(T / 32, 2);                 // c = y @ Wk  (128 CTAs)
        gemm_mma<1, false><<<grid, 256, smemC>>>(yh_p, yl_p, bkh_p, bkl_p, c_p);
    }
    scanA_kernel<<<NTILE, 256>>>();
    scanB_kernel<<<1, 256>>>();
    scanC_kernel<<<NTILE, 256>>>();
    {
        dim3 grid((Bsz * T) / 128, 2);        // out = scramble(S) * (x @ Wq)
        gemm_mma<4, true><<<grid, 256, smemQ>>>(xh_p, xl_p, bqh_p, bql_p, out);
    }
}

// round 9
// speedup vs baseline: 1.5973x; 1.5973x over previous
#include <cuda_runtime.h>
#include <cuda_bf16.h>
#include <cuda_fp16.h>
#include <cstdint>

// ---------------------------------------------------------------------------
// RecurrentRetention: B=16, T=2048, D=256, gamma=0.9
//   vsum[b,t] = x[b,t,:].rowsum(Wv);  y[t,e] = sum_b vsum[b,t]*x[b,t,e]
//   c = y @ Wk;  r[t] = 0.9 r[t-1] + c[t] (exact 3-phase scan) -> S
//   out[b,q,p] = S[8p+(q>>8), q&255] * (x @ Wq)[b,q,p]
// cgemm: bf16 3-pass split (high accuracy -> scan).   qgemm: fp16 2-pass
// (Ah*Bh + Ah*Bl; dropped Al*B ~ 0.39*2^-11 ~ 1.9e-4 rel, tol 1e-3).
// Loaders are the proven R7 synchronous LDG->STS form (cp.async regressed).
// ---------------------------------------------------------------------------

#define Bsz 16
#define T   2048
#define D   256
#define LTILE 8
#define NTILE (T / LTILE)             // 256
#define GL 0.43046721f                // 0.9^8

__device__ float g_wvsum[D];
__device__ float g_c[T * D];
__device__ float g_S[T * D];
__device__ float g_carry[NTILE * D];
__device__ float g_pref[NTILE * D];
__device__ __half        g_xh[Bsz * T * D];   // x as fp16 (hi only)
__device__ __nv_bfloat16 g_yh[T * D];
__device__ __nv_bfloat16 g_yl[T * D];
__device__ __half        g_wqh[D * D];  // Wq^T hi fp16, [n][k]
__device__ __half        g_wql[D * D];  // Wq^T lo fp16
__device__ __nv_bfloat16 g_bkh[D * D];  // Wk^T hi bf16
__device__ __nv_bfloat16 g_bkl[D * D];

__device__ __forceinline__ uint32_t smem_u32(const void* p) {
    uint32_t a;
    asm("{ .reg .u64 t; cvta.to.shared.u64 t, %1; cvt.u32.u64 %0, t; }" : "=r"(a) : "l"(p));
    return a;
}
__device__ __forceinline__ void ldm_x4(uint32_t* r, uint32_t addr) {
    asm volatile("ldmatrix.sync.aligned.m8n8.x4.shared.b16 {%0,%1,%2,%3}, [%4];"
        : "=r"(r[0]), "=r"(r[1]), "=r"(r[2]), "=r"(r[3]) : "r"(addr));
}
__device__ __forceinline__ void ldm_x2(uint32_t* r, uint32_t addr) {
    asm volatile("ldmatrix.sync.aligned.m8n8.x2.shared.b16 {%0,%1}, [%2];"
        : "=r"(r[0]), "=r"(r[1]) : "r"(addr));
}
__device__ __forceinline__ void mma_bf16(float* c, const uint32_t* a, const uint32_t* b) {
    asm volatile(
        "mma.sync.aligned.m16n8k16.row.col.f32.bf16.bf16.f32 "
        "{%0,%1,%2,%3}, {%4,%5,%6,%7}, {%8,%9}, {%0,%1,%2,%3};"
        : "+f"(c[0]), "+f"(c[1]), "+f"(c[2]), "+f"(c[3])
        : "r"(a[0]), "r"(a[1]), "r"(a[2]), "r"(a[3]), "r"(b[0]), "r"(b[1]));
}
__device__ __forceinline__ void mma_fp16(float* c, const uint32_t* a, const uint32_t* b) {
    asm volatile(
        "mma.sync.aligned.m16n8k16.row.col.f32.f16.f16.f32 "
        "{%0,%1,%2,%3}, {%4,%5,%6,%7}, {%8,%9}, {%0,%1,%2,%3};"
        : "+f"(c[0]), "+f"(c[1]), "+f"(c[2]), "+f"(c[3])
        : "r"(a[0]), "r"(a[1]), "r"(a[2]), "r"(a[3]), "r"(b[0]), "r"(b[1]));
}

// ======================= prep: wvsum + weight transpose-splits =============
__global__ void prep_kernel(const float* __restrict__ Wq, const float* __restrict__ Wk,
                            const float* __restrict__ Wv) {
    int bx = blockIdx.x, tid = threadIdx.x;
    if (bx < 256) {                       // Wq^T -> fp16 hi/lo
        int k = bx, n = tid;
        float w = Wq[k * D + n];
        __half h = __float2half_rn(w);
        g_wqh[n * D + k] = h;
        g_wql[n * D + k] = __float2half_rn(w - __half2float(h));
    } else if (bx < 512) {                // Wk^T -> bf16 hi/lo
        int k = bx - 256, n = tid;
        float w = Wk[k * D + n];
        __nv_bfloat16 h = __float2bfloat16(w);
        g_bkh[n * D + k] = h;
        g_bkl[n * D + k] = __float2bfloat16(w - __bfloat162float(h));
    } else {                              // wvsum
        int row  = (bx - 512) * 8 + (tid >> 5);
        int lane = tid & 31;
        float p = 0.f;
        #pragma unroll
        for (int j = lane; j < D; j += 32) p += Wv[row * D + j];
        #pragma unroll
        for (int off = 16; off; off >>= 1) p += __shfl_xor_sync(0xffffffffu, p, off);
        if (lane == 0) g_wvsum[row] = p;
    }
}

// ======================= y kernel: y bf16 split + x fp16 ====================
__global__ void y_kernel(const float* __restrict__ x) {
    __shared__ float xs[Bsz][D];
    __shared__ float vs[Bsz];
    __shared__ float wv[D];
    int t = blockIdx.x;
    int e = threadIdx.x;

    wv[e] = g_wvsum[e];
    #pragma unroll
    for (int b = 0; b < Bsz; ++b) {
        size_t idx = ((size_t)b * T + t) * D + e;
        float v = x[idx];
        xs[b][e] = v;
        g_xh[idx] = __float2half_rn(v);
    }
    __syncthreads();

    int warp = e >> 5, lane = e & 31;
    #pragma unroll
    for (int rep = 0; rep < 2; ++rep) {
        int b = warp * 2 + rep;
        float p = 0.f;
        #pragma unroll
        for (int k = lane; k < D; k += 32) p += xs[b][k] * wv[k];
        #pragma unroll
        for (int off = 16; off; off >>= 1) p += __shfl_xor_sync(0xffffffffu, p, off);
        if (lane == 0) vs[b] = p;
    }
    __syncthreads();

    float acc = 0.f;
    #pragma unroll
    for (int b = 0; b < Bsz; ++b) acc += vs[b] * xs[b][e];
    __nv_bfloat16 h = __float2bfloat16(acc);
    g_yh[t * D + e] = h;
    g_yl[t * D + e] = __float2bfloat16(acc - __bfloat162float(h));
}

#define ROWB 80

// ======================= cgemm: bf16 3-pass, CTA 32x128 ====================
__global__ void __launch_bounds__(256, 2)
cgemm_mma(const __nv_bfloat16* __restrict__ ah, const __nv_bfloat16* __restrict__ al,
          const __nv_bfloat16* __restrict__ bth, const __nv_bfloat16* __restrict__ btl,
          float* __restrict__ C) {
    __shared__ char sAh[32 * ROWB], sAl[32 * ROWB];
    __shared__ char sBh[128 * ROWB], sBl[128 * ROWB];

    int tid = threadIdx.x, wid = tid >> 5, lane = tid & 31;
    int m0 = blockIdx.x * 32, n0 = blockIdx.y * 128;
    int mwarp = (wid & 1) * 16, nwarp = (wid >> 1) * 32;

    uint32_t uAh = smem_u32(sAh), uAl = smem_u32(sAl);
    uint32_t uBh = smem_u32(sBh), uBl = smem_u32(sBl);

    float acc[4][4] = {};
    int arow = lane & 15, ao16 = (lane >> 4) * 16;
    int brow = lane & 7,  bo16 = ((lane >> 3) & 1) * 16;

    for (int kc = 0; kc < 8; ++kc) {
        __syncthreads();
        for (int i = tid; i < 128; i += 256) {
            int r = i >> 2, c16 = i & 3;
            size_t goff = (size_t)(m0 + r) * 256 + kc * 32 + c16 * 8;
            uint32_t so = r * ROWB + c16 * 16;
            *(uint4*)(sAh + so) = *(const uint4*)(ah + goff);
            *(uint4*)(sAl + so) = *(const uint4*)(al + goff);
        }
        #pragma unroll
        for (int j = 0; j < 2; ++j) {
            int i = tid + j * 256;
            int r = i >> 2, c16 = i & 3;
            size_t goff = (size_t)(n0 + r) * 256 + kc * 32 + c16 * 8;
            uint32_t so = r * ROWB + c16 * 16;
            *(uint4*)(sBh + so) = *(const uint4*)(bth + goff);
            *(uint4*)(sBl + so) = *(const uint4*)(btl + goff);
        }
        __syncthreads();

        #pragma unroll
        for (int pass = 0; pass < 3; ++pass) {
            uint32_t uA = (pass < 2) ? uAh : uAl;
            uint32_t uB = (pass == 1) ? uBl : uBh;
            #pragma unroll
            for (int kk = 0; kk < 2; ++kk) {
                uint32_t af[4], bf[4][2];
                ldm_x4(af, uA + (mwarp + arow) * ROWB + kk * 32 + ao16);
                #pragma unroll
                for (int nf = 0; nf < 4; ++nf)
                    ldm_x2(bf[nf], uB + (nwarp + nf * 8 + brow) * ROWB + kk * 32 + bo16);
                #pragma unroll
                for (int nf = 0; nf < 4; ++nf)
                    mma_bf16(acc[nf], af, bf[nf]);
            }
        }
    }

    int tq = lane >> 2, tr = (lane & 3) * 2;
    #pragma unroll
    for (int half = 0; half < 2; ++half) {
        int m = m0 + mwarp + tq + half * 8;
        size_t obase = (size_t)m * 256;
        #pragma unroll
        for (int nf = 0; nf < 4; ++nf) {
            int n = n0 + nwarp + nf * 8 + tr;
            float2 v;
            v.x = acc[nf][half * 2 + 0];
            v.y = acc[nf][half * 2 + 1];
            *(float2*)(C + obase + n) = v;
        }
    }
}

// ======================= qgemm: fp16 2-pass, CTA 128x128, scramble epi =====
__global__ void __launch_bounds__(256, 2)
qgemm_mma(const __half* __restrict__ ah,
          const __half* __restrict__ bth, const __half* __restrict__ btl,
          float* __restrict__ C) {
    __shared__ char sAh[128 * ROWB];
    __shared__ char sBh[128 * ROWB], sBl[128 * ROWB];

    int tid = threadIdx.x, wid = tid >> 5, lane = tid & 31;
    int m0 = blockIdx.x * 128, n0 = blockIdx.y * 128;
    int mwarp = (wid & 1) * 64, nwarp = (wid >> 1) * 32;

    uint32_t uAh = smem_u32(sAh);
    uint32_t uBh = smem_u32(sBh), uBl = smem_u32(sBl);

    float acc[4][4][4] = {};
    int arow = lane & 15, ao16 = (lane >> 4) * 16;
    int brow = lane & 7,  bo16 = ((lane >> 3) & 1) * 16;

    for (int kc = 0; kc < 8; ++kc) {
        __syncthreads();
        #pragma unroll
        for (int j = 0; j < 2; ++j) {       // A hi: 128 rows x 32 k
            int i = tid + j * 256;
            int r = i >> 2, c16 = i & 3;
            size_t goff = (size_t)(m0 + r) * 256 + kc * 32 + c16 * 8;
            uint32_t so = r * ROWB + c16 * 16;
            *(uint4*)(sAh + so) = *(const uint4*)(ah + goff);
        }
        #pragma unroll
        for (int j = 0; j < 2; ++j) {       // B hi/lo: 128 rows x 32 k
            int i = tid + j * 256;
            int r = i >> 2, c16 = i & 3;
            size_t goff = (size_t)(n0 + r) * 256 + kc * 32 + c16 * 8;
            uint32_t so = r * ROWB + c16 * 16;
            *(uint4*)(sBh + so) = *(const uint4*)(bth + goff);
            *(uint4*)(sBl + so) = *(const uint4*)(btl + goff);
        }
        __syncthreads();

        #pragma unroll
        for (int kk = 0; kk < 2; ++kk) {
            uint32_t af[4][4], bfh[4][2], bfl[4][2];
            #pragma unroll
            for (int mf = 0; mf < 4; ++mf)
                ldm_x4(af[mf], uAh + (mwarp + mf * 16 + arow) * ROWB + kk * 32 + ao16);
            #pragma unroll
            for (int nf = 0; nf < 4; ++nf) {
                ldm_x2(bfh[nf], uBh + (nwarp + nf * 8 + brow) * ROWB + kk * 32 + bo16);
                ldm_x2(bfl[nf], uBl + (nwarp + nf * 8 + brow) * ROWB + kk * 32 + bo16);
            }
            #pragma unroll
            for (int mf = 0; mf < 4; ++mf)
                #pragma unroll
                for (int nf = 0; nf < 4; ++nf)
                    mma_fp16(acc[mf][nf], af[mf], bfh[nf]);
            #pragma unroll
            for (int mf = 0; mf < 4; ++mf)
                #pragma unroll
                for (int nf = 0; nf < 4; ++nf)
                    mma_fp16(acc[mf][nf], af[mf], bfl[nf]);
        }
    }

    // ---- epilogue: scramble-scale + float2 stores ----
    int tq = lane >> 2, tr = (lane & 3) * 2;
    #pragma unroll
    for (int mf = 0; mf < 4; ++mf) {
        #pragma unroll
        for (int half = 0; half < 2; ++half) {
            int m = m0 + mwarp + mf * 16 + tq + half * 8;
            size_t obase = (size_t)m * 256;
            int q = m & (T - 1);
            int qh = q >> 8, qc = q & 255;
            #pragma unroll
            for (int nf = 0; nf < 4; ++nf) {
                int n = n0 + nwarp + nf * 8 + tr;
                float s0 = g_S[(((n + 0) << 3) + qh) * 256 + qc];
                float s1 = g_S[(((n + 1) << 3) + qh) * 256 + qc];
                float2 v;
                v.x = acc[mf][nf][half * 2 + 0] * s0;
                v.y = acc[mf][nf][half * 2 + 1] * s1;
                *(float2*)(C + obase + n) = v;
            }
        }
    }
}

// ======================= exact 3-phase scan ================================
__global__ void scanA_kernel() {
    int d = threadIdx.x, g = blockIdx.x;
    int t0 = g * LTILE;
    float s = 0.f;
    #pragma unroll
    for (int i = 0; i < LTILE; ++i) {
        int t = t0 + i;
        float cv = (t == 0) ? 0.f : g_c[t * D + d];
        s = 0.9f * s + cv;
        g_S[t * D + d] = s;
    }
    g_carry[g * D + d] = s;
}
__global__ void scanB_kernel() {
    int d = threadIdx.x;
    float carry = 0.f;
    #pragma unroll 8
    for (int g = 0; g < NTILE; ++g) {
        float tmp = g_carry[g * D + d];
        g_pref[g * D + d] = carry;
        carry = GL * carry + tmp;
    }
}
__global__ void scanC_kernel() {
    int d = threadIdx.x, g = blockIdx.x;
    int t0 = g * LTILE;
    if (g > 0) {
        float pref = g_pref[g * D + d];
        float p = 0.9f;
        #pragma unroll
        for (int i = 0; i < LTILE; ++i) {
            g_S[(t0 + i) * D + d] += p * pref;
            p *= 0.9f;
        }
    } else {
        g_S[d] = g_S[D + d];    // S[0] = r[1]
    }
}

// ======================= launch ============================================
extern "C" void kernel_launch(void* const* d_in, const int* in_sizes, int n_in,
                              void* d_out, int out_size) {
    const float* x  = (const float*)d_in[0];
    const float* Wq = (const float*)d_in[1];
    const float* Wk = (const float*)d_in[2];
    const float* Wv = (const float*)d_in[3];
    float* out = (float*)d_out;

    float* c_p; cudaGetSymbolAddress((void**)&c_p, g_c);
    __half* xh_p;  cudaGetSymbolAddress((void**)&xh_p, g_xh);
    __nv_bfloat16* yh_p; cudaGetSymbolAddress((void**)&yh_p, g_yh);
    __nv_bfloat16* yl_p; cudaGetSymbolAddress((void**)&yl_p, g_yl);
    __half* wqh_p; cudaGetSymbolAddress((void**)&wqh_p, g_wqh);
    __half* wql_p; cudaGetSymbolAddress((void**)&wql_p, g_wql);
    __nv_bfloat16* bkh_p; cudaGetSymbolAddress((void**)&bkh_p, g_bkh);
    __nv_bfloat16* bkl_p; cudaGetSymbolAddress((void**)&bkl_p, g_bkl);

    prep_kernel<<<544, 256>>>(Wq, Wk, Wv);
    y_kernel<<<T, 256>>>(x);
    {
        dim3 grid(T / 32, 2);                 // c = y @ Wk  (128 CTAs)
        cgemm_mma<<<grid, 256>>>(yh_p, yl_p, bkh_p, bkl_p, c_p);
    }
    scanA_kernel<<<NTILE, 256>>>();
    scanB_kernel<<<1, 256>>>();
    scanC_kernel<<<NTILE, 256>>>();
    {
        dim3 grid((Bsz * T) / 128, 2);        // out = scramble(S) * (x @ Wq)
        qgemm_mma<<<grid, 256>>>(xh_p, wqh_p, wql_p, out);
    }
}

// round 10
// speedup vs baseline: 2.4963x; 1.5628x over previous
#include <cuda_runtime.h>
#include <cuda_bf16.h>
#include <cuda_fp16.h>
#include <cstdint>

// ---------------------------------------------------------------------------
// RecurrentRetention: B=16, T=2048, D=256, gamma=0.9
//   vsum[b,t] = x[b,t,:].rowsum(Wv);  y[t,e] = sum_b vsum[b,t]*x[b,t,e]
//   c = y @ Wk;  r[t] = 0.9 r[t-1] + c[t] (exact scan) -> S
//   out[b,q,p] = S[8p+(q>>8), q&255] * (x @ Wq)[b,q,p]
// cgemm: bf16 3-pass split (accuracy -> scan, rel ~6e-6).
// qgemm: fp16 1-pass (xh @ Wqh). Error model (calibrated R9: coeff 0.39):
//   drop Al*B ~2.1e-4 (measured) + drop Ah*Bl ~2.1e-4 indep -> ~3.0e-4 RMS.
// Scan: phase A (tile scan) + fused phase BC (self-computed carry + fixup).
// ---------------------------------------------------------------------------

#define Bsz 16
#define T   2048
#define D   256
#define LTILE 8
#define NTILE (T / LTILE)             // 256
#define GL 0.43046721f                // 0.9^8

__device__ float g_wvsum[D];
__device__ float g_c[T * D];
__device__ float g_S[T * D];
__device__ float g_carry[NTILE * D];
__device__ __half        g_xh[Bsz * T * D];   // x as fp16
__device__ __nv_bfloat16 g_yh[T * D];
__device__ __nv_bfloat16 g_yl[T * D];
__device__ __half        g_wqh[D * D];  // Wq^T fp16, [n][k]
__device__ __nv_bfloat16 g_bkh[D * D];  // Wk^T hi bf16
__device__ __nv_bfloat16 g_bkl[D * D];

__device__ __forceinline__ uint32_t smem_u32(const void* p) {
    uint32_t a;
    asm("{ .reg .u64 t; cvta.to.shared.u64 t, %1; cvt.u32.u64 %0, t; }" : "=r"(a) : "l"(p));
    return a;
}
__device__ __forceinline__ void ldm_x4(uint32_t* r, uint32_t addr) {
    asm volatile("ldmatrix.sync.aligned.m8n8.x4.shared.b16 {%0,%1,%2,%3}, [%4];"
        : "=r"(r[0]), "=r"(r[1]), "=r"(r[2]), "=r"(r[3]) : "r"(addr));
}
__device__ __forceinline__ void ldm_x2(uint32_t* r, uint32_t addr) {
    asm volatile("ldmatrix.sync.aligned.m8n8.x2.shared.b16 {%0,%1}, [%2];"
        : "=r"(r[0]), "=r"(r[1]) : "r"(addr));
}
__device__ __forceinline__ void mma_bf16(float* c, const uint32_t* a, const uint32_t* b) {
    asm volatile(
        "mma.sync.aligned.m16n8k16.row.col.f32.bf16.bf16.f32 "
        "{%0,%1,%2,%3}, {%4,%5,%6,%7}, {%8,%9}, {%0,%1,%2,%3};"
        : "+f"(c[0]), "+f"(c[1]), "+f"(c[2]), "+f"(c[3])
        : "r"(a[0]), "r"(a[1]), "r"(a[2]), "r"(a[3]), "r"(b[0]), "r"(b[1]));
}
__device__ __forceinline__ void mma_fp16(float* c, const uint32_t* a, const uint32_t* b) {
    asm volatile(
        "mma.sync.aligned.m16n8k16.row.col.f32.f16.f16.f32 "
        "{%0,%1,%2,%3}, {%4,%5,%6,%7}, {%8,%9}, {%0,%1,%2,%3};"
        : "+f"(c[0]), "+f"(c[1]), "+f"(c[2]), "+f"(c[3])
        : "r"(a[0]), "r"(a[1]), "r"(a[2]), "r"(a[3]), "r"(b[0]), "r"(b[1]));
}

// ======================= prep: wvsum + weight transpose-splits =============
__global__ void prep_kernel(const float* __restrict__ Wq, const float* __restrict__ Wk,
                            const float* __restrict__ Wv) {
    int bx = blockIdx.x, tid = threadIdx.x;
    if (bx < 256) {                       // Wq^T -> fp16
        int k = bx, n = tid;
        g_wqh[n * D + k] = __float2half_rn(Wq[k * D + n]);
    } else if (bx < 512) {                // Wk^T -> bf16 hi/lo
        int k = bx - 256, n = tid;
        float w = Wk[k * D + n];
        __nv_bfloat16 h = __float2bfloat16(w);
        g_bkh[n * D + k] = h;
        g_bkl[n * D + k] = __float2bfloat16(w - __bfloat162float(h));
    } else {                              // wvsum
        int row  = (bx - 512) * 8 + (tid >> 5);
        int lane = tid & 31;
        float p = 0.f;
        #pragma unroll
        for (int j = lane; j < D; j += 32) p += Wv[row * D + j];
        #pragma unroll
        for (int off = 16; off; off >>= 1) p += __shfl_xor_sync(0xffffffffu, p, off);
        if (lane == 0) g_wvsum[row] = p;
    }
}

// ======================= y kernel: y bf16 split + x fp16 ====================
__global__ void y_kernel(const float* __restrict__ x) {
    __shared__ float xs[Bsz][D];
    __shared__ float vs[Bsz];
    __shared__ float wv[D];
    int t = blockIdx.x;
    int e = threadIdx.x;

    wv[e] = g_wvsum[e];
    #pragma unroll
    for (int b = 0; b < Bsz; ++b) {
        size_t idx = ((size_t)b * T + t) * D + e;
        float v = x[idx];
        xs[b][e] = v;
        g_xh[idx] = __float2half_rn(v);
    }
    __syncthreads();

    int warp = e >> 5, lane = e & 31;
    #pragma unroll
    for (int rep = 0; rep < 2; ++rep) {
        int b = warp * 2 + rep;
        float p = 0.f;
        #pragma unroll
        for (int k = lane; k < D; k += 32) p += xs[b][k] * wv[k];
        #pragma unroll
        for (int off = 16; off; off >>= 1) p += __shfl_xor_sync(0xffffffffu, p, off);
        if (lane == 0) vs[b] = p;
    }
    __syncthreads();

    float acc = 0.f;
    #pragma unroll
    for (int b = 0; b < Bsz; ++b) acc += vs[b] * xs[b][e];
    __nv_bfloat16 h = __float2bfloat16(acc);
    g_yh[t * D + e] = h;
    g_yl[t * D + e] = __float2bfloat16(acc - __bfloat162float(h));
}

#define ROWB 80

// ======================= cgemm: bf16 3-pass, CTA 32x128 ====================
__global__ void __launch_bounds__(256, 2)
cgemm_mma(const __nv_bfloat16* __restrict__ ah, const __nv_bfloat16* __restrict__ al,
          const __nv_bfloat16* __restrict__ bth, const __nv_bfloat16* __restrict__ btl,
          float* __restrict__ C) {
    __shared__ char sAh[32 * ROWB], sAl[32 * ROWB];
    __shared__ char sBh[128 * ROWB], sBl[128 * ROWB];

    int tid = threadIdx.x, wid = tid >> 5, lane = tid & 31;
    int m0 = blockIdx.x * 32, n0 = blockIdx.y * 128;
    int mwarp = (wid & 1) * 16, nwarp = (wid >> 1) * 32;

    uint32_t uAh = smem_u32(sAh), uAl = smem_u32(sAl);
    uint32_t uBh = smem_u32(sBh), uBl = smem_u32(sBl);

    float acc[4][4] = {};
    int arow = lane & 15, ao16 = (lane >> 4) * 16;
    int brow = lane & 7,  bo16 = ((lane >> 3) & 1) * 16;

    for (int kc = 0; kc < 8; ++kc) {
        __syncthreads();
        for (int i = tid; i < 128; i += 256) {
            int r = i >> 2, c16 = i & 3;
            size_t goff = (size_t)(m0 + r) * 256 + kc * 32 + c16 * 8;
            uint32_t so = r * ROWB + c16 * 16;
            *(uint4*)(sAh + so) = *(const uint4*)(ah + goff);
            *(uint4*)(sAl + so) = *(const uint4*)(al + goff);
        }
        #pragma unroll
        for (int j = 0; j < 2; ++j) {
            int i = tid + j * 256;
            int r = i >> 2, c16 = i & 3;
            size_t goff = (size_t)(n0 + r) * 256 + kc * 32 + c16 * 8;
            uint32_t so = r * ROWB + c16 * 16;
            *(uint4*)(sBh + so) = *(const uint4*)(bth + goff);
            *(uint4*)(sBl + so) = *(const uint4*)(btl + goff);
        }
        __syncthreads();

        #pragma unroll
        for (int pass = 0; pass < 3; ++pass) {
            uint32_t uA = (pass < 2) ? uAh : uAl;
            uint32_t uB = (pass == 1) ? uBl : uBh;
            #pragma unroll
            for (int kk = 0; kk < 2; ++kk) {
                uint32_t af[4], bf[4][2];
                ldm_x4(af, uA + (mwarp + arow) * ROWB + kk * 32 + ao16);
                #pragma unroll
                for (int nf = 0; nf < 4; ++nf)
                    ldm_x2(bf[nf], uB + (nwarp + nf * 8 + brow) * ROWB + kk * 32 + bo16);
                #pragma unroll
                for (int nf = 0; nf < 4; ++nf)
                    mma_bf16(acc[nf], af, bf[nf]);
            }
        }
    }

    int tq = lane >> 2, tr = (lane & 3) * 2;
    #pragma unroll
    for (int half = 0; half < 2; ++half) {
        int m = m0 + mwarp + tq + half * 8;
        size_t obase = (size_t)m * 256;
        #pragma unroll
        for (int nf = 0; nf < 4; ++nf) {
            int n = n0 + nwarp + nf * 8 + tr;
            float2 v;
            v.x = acc[nf][half * 2 + 0];
            v.y = acc[nf][half * 2 + 1];
            *(float2*)(C + obase + n) = v;
        }
    }
}

// ======================= qgemm: fp16 1-pass, CTA 128x128, scramble epi =====
__global__ void __launch_bounds__(256, 2)
qgemm_mma(const __half* __restrict__ ah, const __half* __restrict__ bth,
          float* __restrict__ C) {
    __shared__ char sAh[128 * ROWB];
    __shared__ char sBh[128 * ROWB];

    int tid = threadIdx.x, wid = tid >> 5, lane = tid & 31;
    int m0 = blockIdx.x * 128, n0 = blockIdx.y * 128;
    int mwarp = (wid & 1) * 64, nwarp = (wid >> 1) * 32;

    uint32_t uAh = smem_u32(sAh);
    uint32_t uBh = smem_u32(sBh);

    float acc[4][4][4] = {};
    int arow = lane & 15, ao16 = (lane >> 4) * 16;
    int brow = lane & 7,  bo16 = ((lane >> 3) & 1) * 16;

    for (int kc = 0; kc < 8; ++kc) {
        __syncthreads();
        #pragma unroll
        for (int j = 0; j < 2; ++j) {       // A: 128 rows x 32 k
            int i = tid + j * 256;
            int r = i >> 2, c16 = i & 3;
            size_t goff = (size_t)(m0 + r) * 256 + kc * 32 + c16 * 8;
            uint32_t so = r * ROWB + c16 * 16;
            *(uint4*)(sAh + so) = *(const uint4*)(ah + goff);
        }
        #pragma unroll
        for (int j = 0; j < 2; ++j) {       // B: 128 rows x 32 k
            int i = tid + j * 256;
            int r = i >> 2, c16 = i & 3;
            size_t goff = (size_t)(n0 + r) * 256 + kc * 32 + c16 * 8;
            uint32_t so = r * ROWB + c16 * 16;
            *(uint4*)(sBh + so) = *(const uint4*)(bth + goff);
        }
        __syncthreads();

        #pragma unroll
        for (int kk = 0; kk < 2; ++kk) {
            uint32_t af[4][4], bf[4][2];
            #pragma unroll
            for (int mf = 0; mf < 4; ++mf)
                ldm_x4(af[mf], uAh + (mwarp + mf * 16 + arow) * ROWB + kk * 32 + ao16);
            #pragma unroll
            for (int nf = 0; nf < 4; ++nf)
                ldm_x2(bf[nf], uBh + (nwarp + nf * 8 + brow) * ROWB + kk * 32 + bo16);
            #pragma unroll
            for (int mf = 0; mf < 4; ++mf)
                #pragma unroll
                for (int nf = 0; nf < 4; ++nf)
                    mma_fp16(acc[mf][nf], af[mf], bf[nf]);
        }
    }

    // ---- epilogue: scramble-scale + float2 stores ----
    int tq = lane >> 2, tr = (lane & 3) * 2;
    #pragma unroll
    for (int mf = 0; mf < 4; ++mf) {
        #pragma unroll
        for (int half = 0; half < 2; ++half) {
            int m = m0 + mwarp + mf * 16 + tq + half * 8;
            size_t obase = (size_t)m * 256;
            int q = m & (T - 1);
            int qh = q >> 8, qc = q & 255;
            #pragma unroll
            for (int nf = 0; nf < 4; ++nf) {
                int n = n0 + nwarp + nf * 8 + tr;
                float s0 = g_S[(((n + 0) << 3) + qh) * 256 + qc];
                float s1 = g_S[(((n + 1) << 3) + qh) * 256 + qc];
                float2 v;
                v.x = acc[mf][nf][half * 2 + 0] * s0;
                v.y = acc[mf][nf][half * 2 + 1] * s1;
                *(float2*)(C + obase + n) = v;
            }
        }
    }
}

// ======================= exact scan: phase A + fused BC ====================
__global__ void scanA_kernel() {
    int d = threadIdx.x, g = blockIdx.x;
    int t0 = g * LTILE;
    float s = 0.f;
    #pragma unroll
    for (int i = 0; i < LTILE; ++i) {
        int t = t0 + i;
        float cv = (t == 0) ? 0.f : g_c[t * D + d];
        s = 0.9f * s + cv;
        g_S[t * D + d] = s;
    }
    g_carry[g * D + d] = s;
}
// each CTA g reconstructs its incoming carry from g_carry[0..g-1], then fixes
// up its tile. carry array (256KB) is L2-resident and broadcast across CTAs.
__global__ void scanBC_kernel() {
    int d = threadIdx.x, g = blockIdx.x;
    int t0 = g * LTILE;
    if (g == 0) {
        g_S[d] = g_S[D + d];    // S[0] = r[1]
        return;
    }
    float carry = 0.f;
    for (int j = 0; j < g; ++j)
        carry = fmaf(GL, carry, g_carry[j * D + d]);
    float p = 0.9f;
    #pragma unroll
    for (int i = 0; i < LTILE; ++i) {
        g_S[(t0 + i) * D + d] += p * carry;
        p *= 0.9f;
    }
}

// ======================= launch ============================================
extern "C" void kernel_launch(void* const* d_in, const int* in_sizes, int n_in,
                              void* d_out, int out_size) {
    const float* x  = (const float*)d_in[0];
    const float* Wq = (const float*)d_in[1];
    const float* Wk = (const float*)d_in[2];
    const float* Wv = (const float*)d_in[3];
    float* out = (float*)d_out;

    float* c_p; cudaGetSymbolAddress((void**)&c_p, g_c);
    __half* xh_p;  cudaGetSymbolAddress((void**)&xh_p, g_xh);
    __nv_bfloat16* yh_p; cudaGetSymbolAddress((void**)&yh_p, g_yh);
    __nv_bfloat16* yl_p; cudaGetSymbolAddress((void**)&yl_p, g_yl);
    __half* wqh_p; cudaGetSymbolAddress((void**)&wqh_p, g_wqh);
    __nv_bfloat16* bkh_p; cudaGetSymbolAddress((void**)&bkh_p, g_bkh);
    __nv_bfloat16* bkl_p; cudaGetSymbolAddress((void**)&bkl_p, g_bkl);

    prep_kernel<<<544, 256>>>(Wq, Wk, Wv);
    y_kernel<<<T, 256>>>(x);
    {
        dim3 grid(T / 32, 2);                 // c = y @ Wk  (128 CTAs)
        cgemm_mma<<<grid, 256>>>(yh_p, yl_p, bkh_p, bkl_p, c_p);
    }
    scanA_kernel<<<NTILE, 256>>>();
    scanBC_kernel<<<NTILE, 256>>>();
    {
        dim3 grid((Bsz * T) / 128, 2);        // out = scramble(S) * (x @ Wq)
        qgemm_mma<<<grid, 256>>>(xh_p, wqh_p, out);
    }
}

// round 11
// speedup vs baseline: 2.5241x; 1.0111x over previous
#include <cuda_runtime.h>
#include <cuda_bf16.h>
#include <cuda_fp16.h>
#include <cstdint>

// ---------------------------------------------------------------------------
// RecurrentRetention: B=16, T=2048, D=256, gamma=0.9
//   vsum[b,t] = x[b,t,:].rowsum(Wv);  y[t,e] = sum_b vsum[b,t]*x[b,t,e]
//   c = y @ Wk;  r[t] = 0.9 r[t-1] + c[t] -> S   (windowed scan, win=128:
//       gamma^128 ~ 1.4e-6 rel, negligible vs 2.9e-4 budget; tiles<=16 exact)
//   out[b,q,p] = S[8p+(q>>8), q&255] * (x @ Wq)[b,q,p]
// cgemm: bf16 3-pass split (accuracy -> scan).  qgemm: fp16 1-pass with
// register double-buffered mainloop (LDG next chunk before MMA block).
// ---------------------------------------------------------------------------

#define Bsz 16
#define T   2048
#define D   256
#define LTILE 8
#define NTILE (T / LTILE)             // 256
#define WIN 128                       // scan warmup window

__device__ float g_wvsum[D];
__device__ float g_c[T * D];
__device__ float g_S[T * D];
__device__ __half        g_xh[Bsz * T * D];   // x as fp16
__device__ __nv_bfloat16 g_yh[T * D];
__device__ __nv_bfloat16 g_yl[T * D];
__device__ __half        g_wqh[D * D];  // Wq^T fp16, [n][k]
__device__ __nv_bfloat16 g_bkh[D * D];  // Wk^T hi bf16
__device__ __nv_bfloat16 g_bkl[D * D];

__device__ __forceinline__ uint32_t smem_u32(const void* p) {
    uint32_t a;
    asm("{ .reg .u64 t; cvta.to.shared.u64 t, %1; cvt.u32.u64 %0, t; }" : "=r"(a) : "l"(p));
    return a;
}
__device__ __forceinline__ void ldm_x4(uint32_t* r, uint32_t addr) {
    asm volatile("ldmatrix.sync.aligned.m8n8.x4.shared.b16 {%0,%1,%2,%3}, [%4];"
        : "=r"(r[0]), "=r"(r[1]), "=r"(r[2]), "=r"(r[3]) : "r"(addr));
}
__device__ __forceinline__ void ldm_x2(uint32_t* r, uint32_t addr) {
    asm volatile("ldmatrix.sync.aligned.m8n8.x2.shared.b16 {%0,%1}, [%2];"
        : "=r"(r[0]), "=r"(r[1]) : "r"(addr));
}
__device__ __forceinline__ void mma_bf16(float* c, const uint32_t* a, const uint32_t* b) {
    asm volatile(
        "mma.sync.aligned.m16n8k16.row.col.f32.bf16.bf16.f32 "
        "{%0,%1,%2,%3}, {%4,%5,%6,%7}, {%8,%9}, {%0,%1,%2,%3};"
        : "+f"(c[0]), "+f"(c[1]), "+f"(c[2]), "+f"(c[3])
        : "r"(a[0]), "r"(a[1]), "r"(a[2]), "r"(a[3]), "r"(b[0]), "r"(b[1]));
}
__device__ __forceinline__ void mma_fp16(float* c, const uint32_t* a, const uint32_t* b) {
    asm volatile(
        "mma.sync.aligned.m16n8k16.row.col.f32.f16.f16.f32 "
        "{%0,%1,%2,%3}, {%4,%5,%6,%7}, {%8,%9}, {%0,%1,%2,%3};"
        : "+f"(c[0]), "+f"(c[1]), "+f"(c[2]), "+f"(c[3])
        : "r"(a[0]), "r"(a[1]), "r"(a[2]), "r"(a[3]), "r"(b[0]), "r"(b[1]));
}

// ======================= prep: wvsum + weight transpose-splits =============
__global__ void prep_kernel(const float* __restrict__ Wq, const float* __restrict__ Wk,
                            const float* __restrict__ Wv) {
    int bx = blockIdx.x, tid = threadIdx.x;
    if (bx < 256) {                       // Wq^T -> fp16
        int k = bx, n = tid;
        g_wqh[n * D + k] = __float2half_rn(Wq[k * D + n]);
    } else if (bx < 512) {                // Wk^T -> bf16 hi/lo
        int k = bx - 256, n = tid;
        float w = Wk[k * D + n];
        __nv_bfloat16 h = __float2bfloat16(w);
        g_bkh[n * D + k] = h;
        g_bkl[n * D + k] = __float2bfloat16(w - __bfloat162float(h));
    } else {                              // wvsum
        int row  = (bx - 512) * 8 + (tid >> 5);
        int lane = tid & 31;
        float p = 0.f;
        #pragma unroll
        for (int j = lane; j < D; j += 32) p += Wv[row * D + j];
        #pragma unroll
        for (int off = 16; off; off >>= 1) p += __shfl_xor_sync(0xffffffffu, p, off);
        if (lane == 0) g_wvsum[row] = p;
    }
}

// ======================= y kernel: y bf16 split + x fp16 ====================
__global__ void y_kernel(const float* __restrict__ x) {
    __shared__ float xs[Bsz][D];
    __shared__ float vs[Bsz];
    __shared__ float wv[D];
    int t = blockIdx.x;
    int e = threadIdx.x;

    wv[e] = g_wvsum[e];
    #pragma unroll
    for (int b = 0; b < Bsz; ++b) {
        size_t idx = ((size_t)b * T + t) * D + e;
        float v = x[idx];
        xs[b][e] = v;
        g_xh[idx] = __float2half_rn(v);
    }
    __syncthreads();

    int warp = e >> 5, lane = e & 31;
    #pragma unroll
    for (int rep = 0; rep < 2; ++rep) {
        int b = warp * 2 + rep;
        float p = 0.f;
        #pragma unroll
        for (int k = lane; k < D; k += 32) p += xs[b][k] * wv[k];
        #pragma unroll
        for (int off = 16; off; off >>= 1) p += __shfl_xor_sync(0xffffffffu, p, off);
        if (lane == 0) vs[b] = p;
    }
    __syncthreads();

    float acc = 0.f;
    #pragma unroll
    for (int b = 0; b < Bsz; ++b) acc += vs[b] * xs[b][e];
    __nv_bfloat16 h = __float2bfloat16(acc);
    g_yh[t * D + e] = h;
    g_yl[t * D + e] = __float2bfloat16(acc - __bfloat162float(h));
}

#define ROWB 80

// ======================= cgemm: bf16 3-pass, CTA 32x128 ====================
__global__ void __launch_bounds__(256, 2)
cgemm_mma(const __nv_bfloat16* __restrict__ ah, const __nv_bfloat16* __restrict__ al,
          const __nv_bfloat16* __restrict__ bth, const __nv_bfloat16* __restrict__ btl,
          float* __restrict__ C) {
    __shared__ char sAh[32 * ROWB], sAl[32 * ROWB];
    __shared__ char sBh[128 * ROWB], sBl[128 * ROWB];

    int tid = threadIdx.x, wid = tid >> 5, lane = tid & 31;
    int m0 = blockIdx.x * 32, n0 = blockIdx.y * 128;
    int mwarp = (wid & 1) * 16, nwarp = (wid >> 1) * 32;

    uint32_t uAh = smem_u32(sAh), uAl = smem_u32(sAl);
    uint32_t uBh = smem_u32(sBh), uBl = smem_u32(sBl);

    float acc[4][4] = {};
    int arow = lane & 15, ao16 = (lane >> 4) * 16;
    int brow = lane & 7,  bo16 = ((lane >> 3) & 1) * 16;

    for (int kc = 0; kc < 8; ++kc) {
        __syncthreads();
        for (int i = tid; i < 128; i += 256) {
            int r = i >> 2, c16 = i & 3;
            size_t goff = (size_t)(m0 + r) * 256 + kc * 32 + c16 * 8;
            uint32_t so = r * ROWB + c16 * 16;
            *(uint4*)(sAh + so) = *(const uint4*)(ah + goff);
            *(uint4*)(sAl + so) = *(const uint4*)(al + goff);
        }
        #pragma unroll
        for (int j = 0; j < 2; ++j) {
            int i = tid + j * 256;
            int r = i >> 2, c16 = i & 3;
            size_t goff = (size_t)(n0 + r) * 256 + kc * 32 + c16 * 8;
            uint32_t so = r * ROWB + c16 * 16;
            *(uint4*)(sBh + so) = *(const uint4*)(bth + goff);
            *(uint4*)(sBl + so) = *(const uint4*)(btl + goff);
        }
        __syncthreads();

        #pragma unroll
        for (int pass = 0; pass < 3; ++pass) {
            uint32_t uA = (pass < 2) ? uAh : uAl;
            uint32_t uB = (pass == 1) ? uBl : uBh;
            #pragma unroll
            for (int kk = 0; kk < 2; ++kk) {
                uint32_t af[4], bf[4][2];
                ldm_x4(af, uA + (mwarp + arow) * ROWB + kk * 32 + ao16);
                #pragma unroll
                for (int nf = 0; nf < 4; ++nf)
                    ldm_x2(bf[nf], uB + (nwarp + nf * 8 + brow) * ROWB + kk * 32 + bo16);
                #pragma unroll
                for (int nf = 0; nf < 4; ++nf)
                    mma_bf16(acc[nf], af, bf[nf]);
            }
        }
    }

    int tq = lane >> 2, tr = (lane & 3) * 2;
    #pragma unroll
    for (int half = 0; half < 2; ++half) {
        int m = m0 + mwarp + tq + half * 8;
        size_t obase = (size_t)m * 256;
        #pragma unroll
        for (int nf = 0; nf < 4; ++nf) {
            int n = n0 + nwarp + nf * 8 + tr;
            float2 v;
            v.x = acc[nf][half * 2 + 0];
            v.y = acc[nf][half * 2 + 1];
            *(float2*)(C + obase + n) = v;
        }
    }
}

// ======================= qgemm: fp16 1-pass, reg double-buffer =============
__global__ void __launch_bounds__(256, 2)
qgemm_mma(const __half* __restrict__ ah, const __half* __restrict__ bth,
          float* __restrict__ C) {
    __shared__ char sA[2][128 * ROWB];
    __shared__ char sB[2][128 * ROWB];

    int tid = threadIdx.x, wid = tid >> 5, lane = tid & 31;
    int m0 = blockIdx.x * 128, n0 = blockIdx.y * 128;
    int mwarp = (wid & 1) * 64, nwarp = (wid >> 1) * 32;

    uint32_t uA0 = smem_u32(sA[0]), uA1 = smem_u32(sA[1]);
    uint32_t uB0 = smem_u32(sB[0]), uB1 = smem_u32(sB[1]);

    float acc[4][4][4] = {};
    int arow = lane & 15, ao16 = (lane >> 4) * 16;
    int brow = lane & 7,  bo16 = ((lane >> 3) & 1) * 16;

    // per-thread load/store mapping (2 x uint4 each for A and B)
    int r0 = tid >> 2, c0 = (tid & 3);
    int r1 = (tid + 256) >> 2, c1 = ((tid + 256) & 3);
    uint32_t so0 = r0 * ROWB + c0 * 16, so1 = r1 * ROWB + c1 * 16;

    uint4 ra0, ra1, rb0, rb1;
    auto ldg = [&](int kc) {
        ra0 = *(const uint4*)(ah + (size_t)(m0 + r0) * 256 + kc * 32 + c0 * 8);
        ra1 = *(const uint4*)(ah + (size_t)(m0 + r1) * 256 + kc * 32 + c1 * 8);
        rb0 = *(const uint4*)(bth + (size_t)(n0 + r0) * 256 + kc * 32 + c0 * 8);
        rb1 = *(const uint4*)(bth + (size_t)(n0 + r1) * 256 + kc * 32 + c1 * 8);
    };
    auto sts = [&](int st) {
        *(uint4*)(sA[st] + so0) = ra0;
        *(uint4*)(sA[st] + so1) = ra1;
        *(uint4*)(sB[st] + so0) = rb0;
        *(uint4*)(sB[st] + so1) = rb1;
    };

    ldg(0);
    sts(0);

    for (int kc = 0; kc < 8; ++kc) {
        __syncthreads();                     // stage kc&1 populated
        if (kc < 7) ldg(kc + 1);             // LDG latency hides under MMA block
        uint32_t uAh = (kc & 1) ? uA1 : uA0;
        uint32_t uBh = (kc & 1) ? uB1 : uB0;

        #pragma unroll
        for (int kk = 0; kk < 2; ++kk) {
            uint32_t af[4][4], bf[4][2];
            #pragma unroll
            for (int mf = 0; mf < 4; ++mf)
                ldm_x4(af[mf], uAh + (mwarp + mf * 16 + arow) * ROWB + kk * 32 + ao16);
            #pragma unroll
            for (int nf = 0; nf < 4; ++nf)
                ldm_x2(bf[nf], uBh + (nwarp + nf * 8 + brow) * ROWB + kk * 32 + bo16);
            #pragma unroll
            for (int mf = 0; mf < 4; ++mf)
                #pragma unroll
                for (int nf = 0; nf < 4; ++nf)
                    mma_fp16(acc[mf][nf], af[mf], bf[nf]);
        }
        __syncthreads();                     // all reads of next stage's slot done
        if (kc < 7) sts((kc + 1) & 1);
    }

    // ---- epilogue: scramble-scale + float2 stores ----
    int tq = lane >> 2, tr = (lane & 3) * 2;
    #pragma unroll
    for (int mf = 0; mf < 4; ++mf) {
        #pragma unroll
        for (int half = 0; half < 2; ++half) {
            int m = m0 + mwarp + mf * 16 + tq + half * 8;
            size_t obase = (size_t)m * 256;
            int q = m & (T - 1);
            int qh = q >> 8, qc = q & 255;
            #pragma unroll
            for (int nf = 0; nf < 4; ++nf) {
                int n = n0 + nwarp + nf * 8 + tr;
                float s0 = g_S[(((n + 0) << 3) + qh) * 256 + qc];
                float s1 = g_S[(((n + 1) << 3) + qh) * 256 + qc];
                float2 v;
                v.x = acc[mf][nf][half * 2 + 0] * s0;
                v.y = acc[mf][nf][half * 2 + 1] * s1;
                *(float2*)(C + obase + n) = v;
            }
        }
    }
}

// ======================= windowed scan (single kernel) =====================
// tile g covers t in [g*8, g*8+8); warmup from max(1, t0-WIN).
// gamma^WIN ~ 1.4e-6 relative -> negligible; g<=16 tiles are exact.
__global__ void scan_kernel() {
    int d = threadIdx.x, g = blockIdx.x;
    int t0 = g * LTILE;
    int ts = t0 - WIN; if (ts < 1) ts = 1;
    float s = 0.f;
    #pragma unroll 8
    for (int t = ts; t < t0; ++t)           // warmup, no stores
        s = fmaf(0.9f, s, g_c[t * D + d]);
    #pragma unroll
    for (int i = 0; i < LTILE; ++i) {
        int t = t0 + i;
        if (t == 0) { continue; }           // c[0] dropped; S[0] set below
        s = fmaf(0.9f, s, g_c[t * D + d]);
        g_S[t * D + d] = s;
        if (g == 0 && t == 1) g_S[d] = s;   // S[0] = r[1]
    }
}

// ======================= launch ============================================
extern "C" void kernel_launch(void* const* d_in, const int* in_sizes, int n_in,
                              void* d_out, int out_size) {
    const float* x  = (const float*)d_in[0];
    const float* Wq = (const float*)d_in[1];
    const float* Wk = (const float*)d_in[2];
    const float* Wv = (const float*)d_in[3];
    float* out = (float*)d_out;

    float* c_p; cudaGetSymbolAddress((void**)&c_p, g_c);
    __half* xh_p;  cudaGetSymbolAddress((void**)&xh_p, g_xh);
    __nv_bfloat16* yh_p; cudaGetSymbolAddress((void**)&yh_p, g_yh);
    __nv_bfloat16* yl_p; cudaGetSymbolAddress((void**)&yl_p, g_yl);
    __half* wqh_p; cudaGetSymbolAddress((void**)&wqh_p, g_wqh);
    __nv_bfloat16* bkh_p; cudaGetSymbolAddress((void**)&bkh_p, g_bkh);
    __nv_bfloat16* bkl_p; cudaGetSymbolAddress((void**)&bkl_p, g_bkl);

    prep_kernel<<<544, 256>>>(Wq, Wk, Wv);
    y_kernel<<<T, 256>>>(x);
    {
        dim3 grid(T / 32, 2);                 // c = y @ Wk  (128 CTAs)
        cgemm_mma<<<grid, 256>>>(yh_p, yl_p, bkh_p, bkl_p, c_p);
    }
    scan_kernel<<<NTILE, 256>>>();
    {
        dim3 grid((Bsz * T) / 128, 2);        // out = scramble(S) * (x @ Wq)
        qgemm_mma<<<grid, 256>>>(xh_p, wqh_p, out);
    }
}